// round 1
// baseline (speedup 1.0000x reference)
#include <cuda_runtime.h>

#define G   128
#define GG  (G*G)
#define NL  200000
#define HALF 200.0f
#define DX   3.125f
#define INVDX 0.32f
// 2*sigma^2 = KERNEL_WIDTH^2/2 = 9*pi/2 ; ICC = 1/(2 sigma^2) = 2/(9 pi)
#define ICC  0.0707355303f
#define KW2  28.2743338823f   // 9*pi
#define THREADS 512

// Scratch: slice-major layouts for y and z axes (x axis == original layout).
__device__ float g_ty[G*G*G];
__device__ float g_tz[G*G*G];

// t_y[k][i][j] = image[i][k][j]   (rows of 128 floats contiguous both sides)
__global__ void transY_kernel(const float* __restrict__ img) {
    int j = threadIdx.x;      // 0..127
    int k = blockIdx.x;       // 0..127
    int i = blockIdx.y;       // 0..127
    g_ty[(k*G + i)*G + j] = img[(i*G + k)*G + j];
}

// t_z[k][i][j] = image[i][j][k]   (tiled 32x32 transpose of (j,k) per plane i)
__global__ void transZ_kernel(const float* __restrict__ img) {
    __shared__ float tile[32][33];
    int i  = blockIdx.z;
    int jb = blockIdx.x * 32;
    int kb = blockIdx.y * 32;
    int tx = threadIdx.x, ty = threadIdx.y;   // (32, 8)
    #pragma unroll
    for (int r = 0; r < 32; r += 8)
        tile[ty + r][tx] = img[i*GG + (jb + ty + r)*G + (kb + tx)];
    __syncthreads();
    #pragma unroll
    for (int r = 0; r < 32; r += 8)
        g_tz[(kb + ty + r)*GG + i*G + (jb + tx)] = tile[tx][ty + r];
}

__global__ __launch_bounds__(THREADS)
void proj_kernel(const float* __restrict__ image,
                 const float* __restrict__ lx,
                 const float* __restrict__ ly,
                 const float* __restrict__ lz,
                 float* __restrict__ out)
{
    const int axis = blockIdx.y;
    const int idx  = blockIdx.x * THREADS + threadIdx.x;
    const int lor  = idx < NL ? idx : NL - 1;   // tail threads compute dummy, don't store

    const float* lors;
    const float* vol;
    int q0, q1, q2;
    if (axis == 0)      { lors = lx; vol = image; q0 = 1; q1 = 2; q2 = 0; }
    else if (axis == 1) { lors = ly; vol = g_ty;  q0 = 0; q1 = 2; q2 = 1; }
    else                { lors = lz; vol = g_tz;  q0 = 0; q1 = 1; q2 = 2; }

    const float* L6 = lors + lor * 6;
    const float P0x = L6[q0],     P0y = L6[q1],     P0z = L6[q2];
    const float dvx = L6[q0 + 3] - P0x;
    const float dvy = L6[q1 + 3] - P0y;
    const float dvz = L6[q2 + 3] - P0z;
    const float Ln    = sqrtf(dvx*dvx + dvy*dvy + dvz*dvz);
    const float path  = DX * Ln / fabsf(dvz);
    const float invdz = 1.0f / dvz;
    const float Kc2   = __expf(-2.0f * DX * DX * ICC);  // exp(-2 dx^2 / (2 sigma^2))

    float total = 0.0f;

    for (int k = 0; k < G; k++) {
        const float zc = fmaf((float)k + 0.5f, DX, -HALF);
        const float t  = (zc - P0z) * invdz;
        const float xc = fmaf(t, dvx, P0x);
        const float yc = fmaf(t, dvy, P0y);

        const int i0 = (int)floorf((xc + HALF) * INVDX);
        const int j0 = (int)floorf((yc + HALF) * INVDX);

        int jA = (j0 - 2) & ~3;                 // 16B-aligned column base
        jA = jA < 0 ? 0 : (jA > G - 8 ? G - 8 : jA);

        // --- x (row) weight chain: rows i0-2 .. i0+2 ---
        float sx = fmaf((float)(i0 - 2) + 0.5f, DX, -HALF) - xc;
        float wx = __expf(-sx * sx * ICC);
        float rx = __expf(-fmaf(2.0f * sx, DX, DX * DX) * ICC);

        // --- y (col) weight chain: cols jA .. jA+7 ---
        float sy  = fmaf((float)jA + 0.5f, DX, -HALF) - yc;
        float wy0 = __expf(-sy * sy * ICC);
        float ry  = __expf(-fmaf(2.0f * sy, DX, DX * DX) * ICC);

        float wy[8], sy2[8];
        {
            float s = sy, w = wy0, r = ry;
            #pragma unroll
            for (int m = 0; m < 8; m++) {
                wy[m]  = w;
                sy2[m] = s * s;
                w *= r; r *= Kc2; s += DX;
            }
        }

        const float* sbase = vol + k * GG + jA;
        float acc = 0.0f;

        #pragma unroll
        for (int a = 0; a < 5; a++) {
            const int row = i0 - 2 + a;
            const float wA = (row >= 0 && row < G) ? wx : 0.0f;
            const int  rc  = row < 0 ? 0 : (row > G - 1 ? G - 1 : row);

            const float4* rp = (const float4*)(sbase + rc * G);
            const float4 v0 = __ldg(rp);
            const float4 v1 = __ldg(rp + 1);

            const float lim = KW2 - sx * sx;   // cutoff: sy2 + sx2 <= KW2
            float racc;
            racc =      (sy2[0] <= lim ? wy[0] : 0.0f) * v0.x;
            racc = fmaf((sy2[1] <= lim ? wy[1] : 0.0f), v0.y, racc);
            racc = fmaf((sy2[2] <= lim ? wy[2] : 0.0f), v0.z, racc);
            racc = fmaf((sy2[3] <= lim ? wy[3] : 0.0f), v0.w, racc);
            racc = fmaf((sy2[4] <= lim ? wy[4] : 0.0f), v1.x, racc);
            racc = fmaf((sy2[5] <= lim ? wy[5] : 0.0f), v1.y, racc);
            racc = fmaf((sy2[6] <= lim ? wy[6] : 0.0f), v1.z, racc);
            racc = fmaf((sy2[7] <= lim ? wy[7] : 0.0f), v1.w, racc);

            acc = fmaf(wA, racc, acc);

            wx *= rx; rx *= Kc2; sx += DX;
        }

        const bool tv = (t >= 0.0f) && (t <= 1.0f);
        total += tv ? acc : 0.0f;

        __syncthreads();   // keep all warps of the CTA on the same slice (L1 reuse)
    }

    if (idx < NL) out[axis * NL + idx] = total * path;
}

extern "C" void kernel_launch(void* const* d_in, const int* in_sizes, int n_in,
                              void* d_out, int out_size)
{
    (void)in_sizes; (void)n_in; (void)out_size;
    const float* image = (const float*)d_in[0];
    const float* xl    = (const float*)d_in[1];
    const float* yl    = (const float*)d_in[2];
    const float* zl    = (const float*)d_in[3];
    float* out = (float*)d_out;

    transY_kernel<<<dim3(G, G), G>>>(image);
    transZ_kernel<<<dim3(4, 4, G), dim3(32, 8)>>>(image);

    dim3 grid((NL + THREADS - 1) / THREADS, 3);
    proj_kernel<<<grid, THREADS>>>(image, xl, yl, zl, out);
}

// round 2
// speedup vs baseline: 1.6938x; 1.6938x over previous
#include <cuda_runtime.h>
#include <cstdint>

#define G     128
#define GG    (G*G)
#define NL    200000
#define HALF  200.0f
#define DX    3.125f
#define INVDX 0.32f
// 2*sigma^2 = KERNEL_WIDTH^2/2 = 9*pi/2 ; ICC = 2/(9*pi)
#define ICC   0.0707355303f
#define KW2   28.2743338823f   // 9*pi
#define THREADS 512
#define LPT   4                 // lors per thread
#define LPC   (THREADS*LPT)     // 2048 lors per CTA
#define NCTA  ((NL + LPC - 1)/LPC)   // 98 per axis

#define SLICE_BYTES  (GG*4)     // 65536
#define SMEM_BYTES   (128 + 2*SLICE_BYTES)

// Scratch: slice-major layouts for y and z axes (x axis == original layout).
__device__ float g_ty[G*G*G];
__device__ float g_tz[G*G*G];

__global__ void transY_kernel(const float* __restrict__ img) {
    int j = threadIdx.x, k = blockIdx.x, i = blockIdx.y;
    g_ty[(k*G + i)*G + j] = img[(i*G + k)*G + j];
}

__global__ void transZ_kernel(const float* __restrict__ img) {
    __shared__ float tile[32][33];
    int i  = blockIdx.z;
    int jb = blockIdx.x * 32;
    int kb = blockIdx.y * 32;
    int tx = threadIdx.x, ty = threadIdx.y;   // (32, 8)
    #pragma unroll
    for (int r = 0; r < 32; r += 8)
        tile[ty + r][tx] = img[i*GG + (jb + ty + r)*G + (kb + tx)];
    __syncthreads();
    #pragma unroll
    for (int r = 0; r < 32; r += 8)
        g_tz[(kb + ty + r)*GG + i*G + (jb + tx)] = tile[tx][ty + r];
}

// ---------------- TMA / mbarrier helpers ----------------
__device__ __forceinline__ void mbar_init(uint32_t mbar, uint32_t count) {
    asm volatile("mbarrier.init.shared::cta.b64 [%0], %1;" :: "r"(mbar), "r"(count) : "memory");
}
__device__ __forceinline__ void mbar_expect_tx(uint32_t mbar, uint32_t bytes) {
    asm volatile("mbarrier.arrive.expect_tx.shared::cta.b64 _, [%0], %1;"
                 :: "r"(mbar), "r"(bytes) : "memory");
}
__device__ __forceinline__ void mbar_wait(uint32_t mbar, uint32_t phase) {
    asm volatile(
        "{\n\t"
        ".reg .pred P1;\n\t"
        "LAB_WAIT_%=:\n\t"
        "mbarrier.try_wait.parity.acquire.cta.shared::cta.b64 P1, [%0], %1, 0x989680;\n\t"
        "@P1 bra LAB_DONE_%=;\n\t"
        "bra.uni LAB_WAIT_%=;\n\t"
        "LAB_DONE_%=:\n\t"
        "}"
        :: "r"(mbar), "r"(phase) : "memory");
}
__device__ __forceinline__ void bulk_g2s(uint32_t dst, const float* src, uint32_t bytes, uint32_t mbar) {
    asm volatile("cp.async.bulk.shared::cluster.global.mbarrier::complete_tx::bytes [%0], [%1], %2, [%3];"
                 :: "r"(dst), "l"(src), "r"(bytes), "r"(mbar) : "memory");
}

__global__ __launch_bounds__(THREADS)
void proj_kernel(const float* __restrict__ image,
                 const float* __restrict__ lx,
                 const float* __restrict__ ly,
                 const float* __restrict__ lz,
                 float* __restrict__ out)
{
    extern __shared__ __align__(128) unsigned char smem_raw[];
    const uint32_t smem_base = (uint32_t)__cvta_generic_to_shared(smem_raw);
    const uint32_t mbar0 = smem_base;            // two 8-byte mbarriers at offset 0
    float* sbuf = (float*)(smem_raw + 128);      // 2 x 16384 floats

    const int axis = blockIdx.y;
    const int tid  = threadIdx.x;
    const int cta_base = blockIdx.x * LPC;

    const float* lors;
    const float* vol;
    int q0, q1, q2;
    if (axis == 0)      { lors = lx; vol = image; q0 = 1; q1 = 2; q2 = 0; }
    else if (axis == 1) { lors = ly; vol = g_ty;  q0 = 0; q1 = 2; q2 = 1; }
    else                { lors = lz; vol = g_tz;  q0 = 0; q1 = 1; q2 = 2; }

    // -------- per-LOR parameters (registers) --------
    float P0x[LPT], P0y[LPT], P0z[LPT], dvx[LPT], dvy[LPT], invdz[LPT], path[LPT], total[LPT];
    #pragma unroll
    for (int l = 0; l < LPT; l++) {
        int gi = cta_base + l*THREADS + tid;
        int lr = gi < NL ? gi : NL - 1;
        const float* L6 = lors + lr * 6;
        P0x[l] = L6[q0]; P0y[l] = L6[q1]; P0z[l] = L6[q2];
        dvx[l] = L6[q0+3] - P0x[l];
        dvy[l] = L6[q1+3] - P0y[l];
        float dvz = L6[q2+3] - P0z[l];
        float Ln  = sqrtf(dvx[l]*dvx[l] + dvy[l]*dvy[l] + dvz*dvz);
        path[l]  = DX * Ln / fabsf(dvz);
        invdz[l] = 1.0f / dvz;
        total[l] = 0.0f;
    }
    const float Kc2 = __expf(-2.0f * DX * DX * ICC);

    // -------- pipeline prologue --------
    if (tid == 0) {
        mbar_init(mbar0,     1);
        mbar_init(mbar0 + 8, 1);
        asm volatile("fence.proxy.async.shared::cta;" ::: "memory");
    }
    __syncthreads();
    if (tid == 0) {
        mbar_expect_tx(mbar0,     SLICE_BYTES);
        bulk_g2s(smem_base + 128,               vol,      SLICE_BYTES, mbar0);
        mbar_expect_tx(mbar0 + 8, SLICE_BYTES);
        bulk_g2s(smem_base + 128 + SLICE_BYTES, vol + GG, SLICE_BYTES, mbar0 + 8);
    }

    // -------- slice loop --------
    for (int k = 0; k < G; k++) {
        const int b = k & 1;
        mbar_wait(mbar0 + b*8, (k >> 1) & 1);
        const float* sl = sbuf + b * GG;

        const float zc = fmaf((float)k + 0.5f, DX, -HALF);

        #pragma unroll
        for (int l = 0; l < LPT; l++) {
            const float t  = (zc - P0z[l]) * invdz[l];
            const float xc = fmaf(t, dvx[l], P0x[l]);
            const float yc = fmaf(t, dvy[l], P0y[l]);

            const int i0 = __float2int_rd((xc + HALF) * INVDX);
            const int j0 = __float2int_rd((yc + HALF) * INVDX);

            int jA = (j0 - 2) & ~3;
            jA = jA < 0 ? 0 : (jA > G - 8 ? G - 8 : jA);

            float sx = fmaf((float)(i0 - 2) + 0.5f, DX, -HALF) - xc;
            float wx = __expf(-sx * sx * ICC);
            float rx = __expf(-fmaf(2.0f * sx, DX, DX * DX) * ICC);

            float sy  = fmaf((float)jA + 0.5f, DX, -HALF) - yc;
            float w   = __expf(-sy * sy * ICC);
            float r   = __expf(-fmaf(2.0f * sy, DX, DX * DX) * ICC);

            float wy[8], sy2[8];
            {
                float s = sy;
                #pragma unroll
                for (int m = 0; m < 8; m++) {
                    wy[m]  = w;
                    sy2[m] = s * s;
                    w *= r; r *= Kc2; s += DX;
                }
            }

            const float* sb = sl + jA;
            float acc = 0.0f;

            #pragma unroll
            for (int a = 0; a < 5; a++) {
                const int row = i0 - 2 + a;
                const float wA = (row >= 0 && row < G) ? wx : 0.0f;
                const int  rc  = row < 0 ? 0 : (row > G - 1 ? G - 1 : row);

                const float4 v0 = *(const float4*)(sb + rc * G);
                const float4 v1 = *(const float4*)(sb + rc * G + 4);

                const float lim = KW2 - sx * sx;
                float racc;
                racc =      (sy2[0] <= lim ? wy[0] : 0.0f) * v0.x;
                racc = fmaf((sy2[1] <= lim ? wy[1] : 0.0f), v0.y, racc);
                racc = fmaf((sy2[2] <= lim ? wy[2] : 0.0f), v0.z, racc);
                racc = fmaf((sy2[3] <= lim ? wy[3] : 0.0f), v0.w, racc);
                racc = fmaf((sy2[4] <= lim ? wy[4] : 0.0f), v1.x, racc);
                racc = fmaf((sy2[5] <= lim ? wy[5] : 0.0f), v1.y, racc);
                racc = fmaf((sy2[6] <= lim ? wy[6] : 0.0f), v1.z, racc);
                racc = fmaf((sy2[7] <= lim ? wy[7] : 0.0f), v1.w, racc);

                acc = fmaf(wA, racc, acc);

                wx *= rx; rx *= Kc2; sx += DX;
            }

            const bool tv = (t >= 0.0f) && (t <= 1.0f);
            total[l] += tv ? acc : 0.0f;
        }

        __syncthreads();   // all reads of buffer b for slice k complete
        if (tid == 0 && k + 2 < G) {
            mbar_expect_tx(mbar0 + b*8, SLICE_BYTES);
            bulk_g2s(smem_base + 128 + b*SLICE_BYTES, vol + (size_t)(k+2)*GG, SLICE_BYTES, mbar0 + b*8);
        }
    }

    // -------- store --------
    #pragma unroll
    for (int l = 0; l < LPT; l++) {
        int gi = cta_base + l*THREADS + tid;
        if (gi < NL) out[axis * NL + gi] = total[l] * path[l];
    }
}

extern "C" void kernel_launch(void* const* d_in, const int* in_sizes, int n_in,
                              void* d_out, int out_size)
{
    (void)in_sizes; (void)n_in; (void)out_size;
    const float* image = (const float*)d_in[0];
    const float* xl    = (const float*)d_in[1];
    const float* yl    = (const float*)d_in[2];
    const float* zl    = (const float*)d_in[3];
    float* out = (float*)d_out;

    static bool attr_set = false;
    if (!attr_set) {
        cudaFuncSetAttribute(proj_kernel, cudaFuncAttributeMaxDynamicSharedMemorySize, SMEM_BYTES);
        attr_set = true;
    }

    transY_kernel<<<dim3(G, G), G>>>(image);
    transZ_kernel<<<dim3(4, 4, G), dim3(32, 8)>>>(image);

    dim3 grid(NCTA, 3);
    proj_kernel<<<grid, THREADS, SMEM_BYTES>>>(image, xl, yl, zl, out);
}

// round 3
// speedup vs baseline: 2.9770x; 1.7575x over previous
#include <cuda_runtime.h>
#include <cuda_fp16.h>
#include <cstdint>

#define G     128
#define GG    (G*G)
#define NL    200000
#define HALF  200.0f
#define DX    3.125f
#define INVDX 0.32f
// 2*sigma^2 = KERNEL_WIDTH^2/2 = 9*pi/2 ; ICC = 2/(9*pi)
#define ICC   0.0707355303f
#define KW2   28.2743338823f   // 9*pi
#define TFRAC 0.2016f          // frac threshold for 4-wide window anchor
#define THREADS 512
#define LPT   4
#define LPC   (THREADS*LPT)            // 2048
#define NCTA  ((NL + LPC - 1)/LPC)     // 98 per axis -> 294 CTAs -> 1 wave @ 2 CTA/SM

#define SLICE_BYTES  (GG*2)            // 32768 (fp16)
#define SMEM_BYTES   (128 + 2*SLICE_BYTES)

// fp16 slice-major volumes for each axis
__device__ __half g_tx[G*G*G];
__device__ __half g_ty[G*G*G];
__device__ __half g_tz[G*G*G];

__global__ void transX_kernel(const float* __restrict__ img) {
    int idx = blockIdx.x * 256 + threadIdx.x;
    g_tx[idx] = __float2half(img[idx]);
}

// t_y[k][i][j] = image[i][k][j]
__global__ void transY_kernel(const float* __restrict__ img) {
    int j = threadIdx.x, k = blockIdx.x, i = blockIdx.y;
    g_ty[(k*G + i)*G + j] = __float2half(img[(i*G + k)*G + j]);
}

// t_z[k][i][j] = image[i][j][k]
__global__ void transZ_kernel(const float* __restrict__ img) {
    __shared__ float tile[32][33];
    int i  = blockIdx.z;
    int jb = blockIdx.x * 32;
    int kb = blockIdx.y * 32;
    int tx = threadIdx.x, ty = threadIdx.y;   // (32, 8)
    #pragma unroll
    for (int r = 0; r < 32; r += 8)
        tile[ty + r][tx] = img[i*GG + (jb + ty + r)*G + (kb + tx)];
    __syncthreads();
    #pragma unroll
    for (int r = 0; r < 32; r += 8)
        g_tz[(kb + ty + r)*GG + i*G + (jb + tx)] = __float2half(tile[tx][ty + r]);
}

// ---------------- TMA / mbarrier helpers ----------------
__device__ __forceinline__ void mbar_init(uint32_t mbar, uint32_t count) {
    asm volatile("mbarrier.init.shared::cta.b64 [%0], %1;" :: "r"(mbar), "r"(count) : "memory");
}
__device__ __forceinline__ void mbar_expect_tx(uint32_t mbar, uint32_t bytes) {
    asm volatile("mbarrier.arrive.expect_tx.shared::cta.b64 _, [%0], %1;"
                 :: "r"(mbar), "r"(bytes) : "memory");
}
__device__ __forceinline__ void mbar_wait(uint32_t mbar, uint32_t phase) {
    asm volatile(
        "{\n\t"
        ".reg .pred P1;\n\t"
        "LAB_WAIT_%=:\n\t"
        "mbarrier.try_wait.parity.acquire.cta.shared::cta.b64 P1, [%0], %1, 0x989680;\n\t"
        "@P1 bra LAB_DONE_%=;\n\t"
        "bra.uni LAB_WAIT_%=;\n\t"
        "LAB_DONE_%=:\n\t"
        "}"
        :: "r"(mbar), "r"(phase) : "memory");
}
__device__ __forceinline__ void bulk_g2s(uint32_t dst, const void* src, uint32_t bytes, uint32_t mbar) {
    asm volatile("cp.async.bulk.shared::cluster.global.mbarrier::complete_tx::bytes [%0], [%1], %2, [%3];"
                 :: "r"(dst), "l"(src), "r"(bytes), "r"(mbar) : "memory");
}

__global__ __launch_bounds__(THREADS, 2)
void proj_kernel(const float* __restrict__ lx,
                 const float* __restrict__ ly,
                 const float* __restrict__ lz,
                 float* __restrict__ out)
{
    extern __shared__ __align__(128) unsigned char smem_raw[];
    const uint32_t smem_base = (uint32_t)__cvta_generic_to_shared(smem_raw);
    const uint32_t mbar0 = smem_base;
    __half* sbuf = (__half*)(smem_raw + 128);

    const int axis = blockIdx.y;
    const int tid  = threadIdx.x;
    const int cta_base = blockIdx.x * LPC;

    const float* lors;
    const __half* vol;
    int q0, q1, q2;
    if (axis == 0)      { lors = lx; vol = g_tx; q0 = 1; q1 = 2; q2 = 0; }
    else if (axis == 1) { lors = ly; vol = g_ty; q0 = 0; q1 = 2; q2 = 1; }
    else                { lors = lz; vol = g_tz; q0 = 0; q1 = 1; q2 = 2; }

    // per-LOR params.  NOTE: lors[:,q2] = -HALF, lors[:,q2+3] = +HALF exactly,
    // so dvz = 400 and t_k = (k+0.5)*DX/400 is LOR-independent.
    float P0x[LPT], P0y[LPT], dvx[LPT], dvy[LPT], total[LPT];
    #pragma unroll
    for (int l = 0; l < LPT; l++) {
        int gi = cta_base + l*THREADS + tid;
        int lr = gi < NL ? gi : NL - 1;
        const float* L6 = lors + lr * 6;
        P0x[l] = L6[q0]; P0y[l] = L6[q1];
        dvx[l] = L6[q0+3] - P0x[l];
        dvy[l] = L6[q1+3] - P0y[l];
        total[l] = 0.0f;
        (void)q2;
    }
    const float Kc2 = __expf(-2.0f * DX * DX * ICC);

    if (tid == 0) {
        mbar_init(mbar0,     1);
        mbar_init(mbar0 + 8, 1);
        asm volatile("fence.proxy.async.shared::cta;" ::: "memory");
    }
    __syncthreads();
    if (tid == 0) {
        mbar_expect_tx(mbar0,     SLICE_BYTES);
        bulk_g2s(smem_base + 128,               vol,      SLICE_BYTES, mbar0);
        mbar_expect_tx(mbar0 + 8, SLICE_BYTES);
        bulk_g2s(smem_base + 128 + SLICE_BYTES, vol + GG, SLICE_BYTES, mbar0 + 8);
    }

    for (int k = 0; k < G; k++) {
        const int b = k & 1;
        mbar_wait(mbar0 + b*8, (k >> 1) & 1);
        const __half2* slice = (const __half2*)(sbuf + b * GG);

        const float tk = ((float)k + 0.5f) * (DX / 400.0f);

        #pragma unroll
        for (int l = 0; l < LPT; l++) {
            const float xc = fmaf(tk, dvx[l], P0x[l]);
            const float yc = fmaf(tk, dvy[l], P0y[l]);

            const float ux = fmaf(xc, INVDX, HALF*INVDX);
            const float i0f = floorf(ux);
            const float fx  = ux - i0f;
            int alo = (int)i0f - 2 + (fx < TFRAC ? 0 : 1);
            alo = min(max(alo, 0), G - 4);

            const float uy = fmaf(yc, INVDX, HALF*INVDX);
            const float j0f = floorf(uy);
            const float fy  = uy - j0f;
            int clo = (int)j0f - 2 + (fy < TFRAC ? 0 : 1);
            clo = min(max(clo, 0), G - 6);
            const int cE = clo & ~1;

            // column weight table (6 cols from cE)
            float s = fmaf((float)cE + 0.5f, DX, -HALF) - yc;
            float w = __expf(-s * s * ICC);
            float r = __expf(-fmaf(2.0f * s, DX, DX * DX) * ICC);
            float wy[6], sy2[6];
            #pragma unroll
            for (int m = 0; m < 6; m++) {
                wy[m]  = w;
                sy2[m] = s * s;
                w *= r; r *= Kc2; s += DX;
            }

            // row weight chain (4 rows from alo)
            float sx = fmaf((float)alo + 0.5f, DX, -HALF) - xc;
            float wx = __expf(-sx * sx * ICC);
            float rx = __expf(-fmaf(2.0f * sx, DX, DX * DX) * ICC);

            const __half2* rp = slice + alo * (G/2) + (cE >> 1);
            float acc = 0.0f;

            #pragma unroll
            for (int a = 0; a < 4; a++) {
                const float2 f0 = __half22float2(rp[0]);
                const float2 f1 = __half22float2(rp[1]);
                const float2 f2 = __half22float2(rp[2]);

                const float lim = fmaf(-sx, sx, KW2);
                float racc;
                racc =      (sy2[0] <= lim ? wy[0] : 0.0f) * f0.x;
                racc = fmaf((sy2[1] <= lim ? wy[1] : 0.0f), f0.y, racc);
                racc = fmaf((sy2[2] <= lim ? wy[2] : 0.0f), f1.x, racc);
                racc = fmaf((sy2[3] <= lim ? wy[3] : 0.0f), f1.y, racc);
                racc = fmaf((sy2[4] <= lim ? wy[4] : 0.0f), f2.x, racc);
                racc = fmaf((sy2[5] <= lim ? wy[5] : 0.0f), f2.y, racc);

                acc = fmaf(wx, racc, acc);

                wx *= rx; rx *= Kc2; sx += DX;
                rp += G/2;
            }
            total[l] += acc;
        }

        __syncthreads();
        if (tid == 0 && k + 2 < G) {
            mbar_expect_tx(mbar0 + b*8, SLICE_BYTES);
            bulk_g2s(smem_base + 128 + b*SLICE_BYTES, vol + (size_t)(k+2)*GG, SLICE_BYTES, mbar0 + b*8);
        }
    }

    #pragma unroll
    for (int l = 0; l < LPT; l++) {
        int gi = cta_base + l*THREADS + tid;
        if (gi < NL) {
            // path = DX * |LOR| / dvz, dvz = 400
            float Ln = sqrtf(fmaf(dvx[l], dvx[l], fmaf(dvy[l], dvy[l], 160000.0f)));
            out[axis * NL + gi] = total[l] * (DX / 400.0f) * Ln;
        }
    }
}

extern "C" void kernel_launch(void* const* d_in, const int* in_sizes, int n_in,
                              void* d_out, int out_size)
{
    (void)in_sizes; (void)n_in; (void)out_size;
    const float* image = (const float*)d_in[0];
    const float* xl    = (const float*)d_in[1];
    const float* yl    = (const float*)d_in[2];
    const float* zl    = (const float*)d_in[3];
    float* out = (float*)d_out;

    static bool attr_set = false;
    if (!attr_set) {
        cudaFuncSetAttribute(proj_kernel, cudaFuncAttributeMaxDynamicSharedMemorySize, SMEM_BYTES);
        attr_set = true;
    }

    transX_kernel<<<G*G*G/256, 256>>>(image);
    transY_kernel<<<dim3(G, G), G>>>(image);
    transZ_kernel<<<dim3(4, 4, G), dim3(32, 8)>>>(image);

    dim3 grid(NCTA, 3);
    proj_kernel<<<grid, THREADS, SMEM_BYTES>>>(xl, yl, zl, out);
}

// round 4
// speedup vs baseline: 3.5208x; 1.1827x over previous
#include <cuda_runtime.h>
#include <cuda_fp16.h>
#include <cstdint>

#define G     128
#define GG    (G*G)
#define RS    130              // padded row stride in halfs (65 half2 -> conflict-free-ish)
#define RS2   65               // row stride in half2
#define NL    200000
#define HALF  200.0f
#define DX    3.125f
#define INVDX 0.32f
#define DX2   9.765625f
#define TWODX2 19.53125f
// C2LOG = ICC * log2(e) = (2/(9*pi)) * 1.4426950409
#define C2LOG 0.1020498f
#define KW2   28.2743338823f   // 9*pi
#define TFRAC 0.2016f
#define THREADS 512
#define LPT   4
#define LPC   (THREADS*LPT)            // 2048
#define NCTA  ((NL + LPC - 1)/LPC)     // 98 per axis

#define SLICE_BYTES  (G*RS*2)          // 33280
#define SMEM_BYTES   (128 + 2*SLICE_BYTES)

// fp16 slice-major padded volumes, one per axis
__device__ __half g_tx[G*G*RS];
__device__ __half g_ty[G*G*RS];
__device__ __half g_tz[G*G*RS];

// One fused transform: read image[i][j][k] tile once, emit all three layouts.
//  g_tx[(i*G + j)*RS + k] = img[i][j][k]   (direct)
//  g_ty[(j*G + i)*RS + k] = img[i][j][k]   (direct)
//  g_tz[(k*G + i)*RS + j] = img[i][j][k]   (j/k transpose via smem tile)
__global__ void trans_all_kernel(const float* __restrict__ img) {
    __shared__ float tile[32][33];
    const int i  = blockIdx.z;
    const int jb = blockIdx.x * 32;
    const int kb = blockIdx.y * 32;
    const int tx = threadIdx.x, ty = threadIdx.y;   // (32, 8)
    #pragma unroll
    for (int r = 0; r < 32; r += 8) {
        const int j = jb + ty + r;
        const float v = img[(i*G + j)*G + kb + tx];
        tile[ty + r][tx] = v;
        const __half h = __float2half(v);
        g_tx[(i*G + j)*RS + kb + tx] = h;
        g_ty[(j*G + i)*RS + kb + tx] = h;
    }
    __syncthreads();
    #pragma unroll
    for (int r = 0; r < 32; r += 8)
        g_tz[((kb + ty + r)*G + i)*RS + jb + tx] = __float2half(tile[tx][ty + r]);
}

// ---------------- TMA / mbarrier helpers ----------------
__device__ __forceinline__ void mbar_init(uint32_t mbar, uint32_t count) {
    asm volatile("mbarrier.init.shared::cta.b64 [%0], %1;" :: "r"(mbar), "r"(count) : "memory");
}
__device__ __forceinline__ void mbar_expect_tx(uint32_t mbar, uint32_t bytes) {
    asm volatile("mbarrier.arrive.expect_tx.shared::cta.b64 _, [%0], %1;"
                 :: "r"(mbar), "r"(bytes) : "memory");
}
__device__ __forceinline__ void mbar_wait(uint32_t mbar, uint32_t phase) {
    asm volatile(
        "{\n\t"
        ".reg .pred P1;\n\t"
        "LAB_WAIT_%=:\n\t"
        "mbarrier.try_wait.parity.acquire.cta.shared::cta.b64 P1, [%0], %1, 0x989680;\n\t"
        "@P1 bra LAB_DONE_%=;\n\t"
        "bra.uni LAB_WAIT_%=;\n\t"
        "LAB_DONE_%=:\n\t"
        "}"
        :: "r"(mbar), "r"(phase) : "memory");
}
__device__ __forceinline__ void bulk_g2s(uint32_t dst, const void* src, uint32_t bytes, uint32_t mbar) {
    asm volatile("cp.async.bulk.shared::cluster.global.mbarrier::complete_tx::bytes [%0], [%1], %2, [%3];"
                 :: "r"(dst), "l"(src), "r"(bytes), "r"(mbar) : "memory");
}

__global__ __launch_bounds__(THREADS, 2)
void proj_kernel(const float* __restrict__ lx,
                 const float* __restrict__ ly,
                 const float* __restrict__ lz,
                 float* __restrict__ out)
{
    extern __shared__ __align__(128) unsigned char smem_raw[];
    const uint32_t smem_base = (uint32_t)__cvta_generic_to_shared(smem_raw);
    const uint32_t mbar0 = smem_base;
    __half* sbuf = (__half*)(smem_raw + 128);

    const int axis = blockIdx.y;
    const int tid  = threadIdx.x;
    const int cta_base = blockIdx.x * LPC;

    const float* lors;
    const __half* vol;
    int q0, q1;
    if (axis == 0)      { lors = lx; vol = g_tx; q0 = 1; q1 = 2; }
    else if (axis == 1) { lors = ly; vol = g_ty; q0 = 0; q1 = 2; }
    else                { lors = lz; vol = g_tz; q0 = 0; q1 = 1; }

    // per-LOR params. lors scan-axis coords are exactly -HALF/+HALF -> dvz = 400,
    // t_k = (k+0.5)*DX/400 is LOR-independent.
    float P0x[LPT], P0y[LPT], dvx[LPT], dvy[LPT], total[LPT];
    #pragma unroll
    for (int l = 0; l < LPT; l++) {
        int gi = cta_base + l*THREADS + tid;
        int lr = gi < NL ? gi : NL - 1;
        const float* L6 = lors + lr * 6;
        P0x[l] = L6[q0]; P0y[l] = L6[q1];
        dvx[l] = L6[q0+3] - P0x[l];
        dvy[l] = L6[q1+3] - P0y[l];
        total[l] = 0.0f;
    }

    const __half2 nCh2 = __float2half2_rn(-C2LOG);
    const __half2 zero2 = __float2half2_rn(0.0f);

    if (tid == 0) {
        mbar_init(mbar0,     1);
        mbar_init(mbar0 + 8, 1);
        asm volatile("fence.proxy.async.shared::cta;" ::: "memory");
    }
    __syncthreads();
    if (tid == 0) {
        mbar_expect_tx(mbar0,     SLICE_BYTES);
        bulk_g2s(smem_base + 128,               vol,          SLICE_BYTES, mbar0);
        mbar_expect_tx(mbar0 + 8, SLICE_BYTES);
        bulk_g2s(smem_base + 128 + SLICE_BYTES, vol + G*RS,   SLICE_BYTES, mbar0 + 8);
    }

    for (int k = 0; k < G; k++) {
        const int b = k & 1;
        mbar_wait(mbar0 + b*8, (k >> 1) & 1);
        const __half2* slice = (const __half2*)(sbuf + b * (G*RS));

        const float tk = ((float)k + 0.5f) * (DX / 400.0f);

        #pragma unroll
        for (int l = 0; l < LPT; l++) {
            const float xc = fmaf(tk, dvx[l], P0x[l]);
            const float yc = fmaf(tk, dvy[l], P0y[l]);

            // anchors: alo = floor(ux - TFRAC) - 1, clamped
            const float ux = fmaf(xc, INVDX, HALF*INVDX);
            int alo = __float2int_rd(ux - TFRAC) - 1;
            alo = min(max(alo, 0), G - 4);
            const float uy = fmaf(yc, INVDX, HALF*INVDX);
            int clo = __float2int_rd(uy - TFRAC) - 1;
            clo = min(max(clo, 0), G - 6);
            const int cE = clo & ~1;

            const float sx0 = fmaf((float)alo, DX, 0.5f*DX - HALF) - xc;
            const float sy0 = fmaf((float)cE,  DX, 0.5f*DX - HALF) - yc;

            // column sy^2 chain (float), packed to half2 pairs
            const float q0f = sy0 * sy0;
            float u = fmaf(2.0f*DX, sy0, DX2);
            const float q1f = q0f + u; u += TWODX2;
            const float q2f = q1f + u; u += TWODX2;
            const float q3f = q2f + u; u += TWODX2;
            const float q4f = q3f + u; u += TWODX2;
            const float q5f = q4f + u;
            const __half2 S0 = __floats2half2_rn(q0f, q1f);
            const __half2 S1 = __floats2half2_rn(q2f, q3f);
            const __half2 S2 = __floats2half2_rn(q4f, q5f);
            const __half2 P0 = h2exp2(__hmul2(S0, nCh2));
            const __half2 P1 = h2exp2(__hmul2(S1, nCh2));
            const __half2 P2 = h2exp2(__hmul2(S2, nCh2));

            // row sx^2 chain (float)
            float px = sx0 * sx0;
            float vx = fmaf(2.0f*DX, sx0, DX2);

            const __half2* rp = slice + alo * RS2 + (cE >> 1);
            __half2 acc2 = zero2;

            #pragma unroll
            for (int a = 0; a < 4; a++) {
                const __half2 V0 = rp[0];
                const __half2 V1 = rp[1];
                const __half2 V2 = rp[2];

                const __half2 lim2 = __float2half2_rn(KW2 - px);
                const __half2 wx2  = __float2half2_rn(exp2f(-C2LOG * px));

                __half2 r2 = __hmul2(__hmul2(__hle2(S0, lim2), P0), V0);
                r2 = __hfma2(__hmul2(__hle2(S1, lim2), P1), V1, r2);
                r2 = __hfma2(__hmul2(__hle2(S2, lim2), P2), V2, r2);
                acc2 = __hfma2(wx2, r2, acc2);

                px += vx; vx += TWODX2;
                rp += RS2;
            }

            const float2 f2 = __half22float2(acc2);
            total[l] += f2.x + f2.y;
        }

        __syncthreads();
        if (tid == 0 && k + 2 < G) {
            mbar_expect_tx(mbar0 + b*8, SLICE_BYTES);
            bulk_g2s(smem_base + 128 + b*SLICE_BYTES,
                     vol + (size_t)(k+2)*(G*RS), SLICE_BYTES, mbar0 + b*8);
        }
    }

    #pragma unroll
    for (int l = 0; l < LPT; l++) {
        int gi = cta_base + l*THREADS + tid;
        if (gi < NL) {
            float Ln = sqrtf(fmaf(dvx[l], dvx[l], fmaf(dvy[l], dvy[l], 160000.0f)));
            out[axis * NL + gi] = total[l] * (DX / 400.0f) * Ln;
        }
    }
}

extern "C" void kernel_launch(void* const* d_in, const int* in_sizes, int n_in,
                              void* d_out, int out_size)
{
    (void)in_sizes; (void)n_in; (void)out_size;
    const float* image = (const float*)d_in[0];
    const float* xl    = (const float*)d_in[1];
    const float* yl    = (const float*)d_in[2];
    const float* zl    = (const float*)d_in[3];
    float* out = (float*)d_out;

    static bool attr_set = false;
    if (!attr_set) {
        cudaFuncSetAttribute(proj_kernel, cudaFuncAttributeMaxDynamicSharedMemorySize, SMEM_BYTES);
        attr_set = true;
    }

    trans_all_kernel<<<dim3(4, 4, G), dim3(32, 8)>>>(image);

    dim3 grid(NCTA, 3);
    proj_kernel<<<grid, THREADS, SMEM_BYTES>>>(xl, yl, zl, out);
}